// round 15
// baseline (speedup 1.0000x reference)
#include <cuda_runtime.h>
#include <cuda_fp16.h>
#include <cstdint>
#include <cstring>

#define D     128
#define LDIM  64
#define NMAX  50000
#define EMAX  625000
#define EPS   1e-5f
#define SLOPE 0.01f

// ---------------- scratch (static device globals; no allocation) ----------------
__device__ __half   g_h   [NMAX * D];        // GEMM output, fp16, pre-scaled by dinv
__device__ __half   g_aggA[NMAX * D];        // prop output (pre-BN), fp16
__device__ __half   g_aggB[NMAX * D];
__device__ float    g_x1  [NMAX * D];
__device__ float    g_x2  [NMAX * D];
__device__ float    g_dinv[NMAX];
__device__ int      g_counts[NMAX];          // invariant: all-zero at entry
__device__ int      g_rowptr[NMAX + 1];
__device__ int      g_linc[NMAX];
__device__ int      g_bsums[128];
__device__ int      g_wofs[NMAX];
__device__ int      g_col[EMAX];
__device__ float    g_stats[3 * 2 * D];
__device__ uint32_t g_Wfrag[4 * 8192];       // 4 matrices, fp16 fragment-major
__device__ float    g_bcat[D];

// ---------------- graph preprocessing ----------------
__global__ void k_count(const int* __restrict__ dst, int* counts, int e) {
    int i = blockIdx.x * blockDim.x + threadIdx.x;
    if (i < e) atomicAdd(&counts[dst[i]], 1);
}

// per-block (1024) inclusive scan; block 0 also zeroes BN stats
__global__ __launch_bounds__(1024) void k_scan1(const int* __restrict__ counts,
                                                int* linc, int* bsums,
                                                float* stats, int n) {
    __shared__ int ws[32];
    const int tid = threadIdx.x, lane = tid & 31, wid = tid >> 5;
    if (blockIdx.x == 0 && tid < 3 * 2 * D) stats[tid] = 0.f;
    int i = blockIdx.x * 1024 + tid;
    int v = (i < n) ? counts[i] : 0;
    int s = v;
    #pragma unroll
    for (int off = 1; off < 32; off <<= 1) {
        int t = __shfl_up_sync(0xffffffffu, s, off);
        if (lane >= off) s += t;
    }
    if (lane == 31) ws[wid] = s;
    __syncthreads();
    if (wid == 0) {
        int t2 = ws[lane];
        #pragma unroll
        for (int off = 1; off < 32; off <<= 1) {
            int t = __shfl_up_sync(0xffffffffu, t2, off);
            if (lane >= off) t2 += t;
        }
        ws[lane] = t2;
    }
    __syncthreads();
    int inc = s + (wid ? ws[wid - 1] : 0);
    if (i < n) linc[i] = inc;
    if (tid == 1023) bsums[blockIdx.x] = inc;
}

// finalize rowptr/wofs/dinv + inline scan2 + restore counts + pre-pack weights
// into fp16 fragment-major layout: idx = ((kt*8+np)*32+ln)*4 + (nt&1)*2 + r
__global__ __launch_bounds__(256) void k_aux_pack(
        const int* __restrict__ linc, const int* __restrict__ bsums,
        int* counts, int* rowptr, int* wofs, float* dinv,
        const float* __restrict__ Ws,
        const float* __restrict__ Wmu, const float* __restrict__ Wlv,
        const float* __restrict__ bmu, const float* __restrict__ blv,
        uint32_t* Wfrag, float* bcat, int n) {
    __shared__ int s_pre;
    const int tid = threadIdx.x;
    if (tid == 0) s_pre = 0;
    __syncthreads();
    const int j = (int)(blockIdx.x >> 2);
    if (tid < j) atomicAdd(&s_pre, bsums[tid]);
    __syncthreads();
    const int pre = s_pre;
    int i = blockIdx.x * 256 + tid;
    if (i < n) {
        int c = counts[i];
        int rp1 = pre + linc[i];
        rowptr[i + 1] = rp1;
        wofs[i] = rp1 - c;
        dinv[i] = rsqrtf((float)(c + 1));     // +1 self-loop
        counts[i] = 0;
        if (i == 0) rowptr[0] = 0;
    }
    if (i < 4 * 8192) {
        int l   = i >> 13;
        int r13 = i & 8191;
        int reg = r13 & 3;
        int ln  = (r13 >> 2) & 31;
        int np  = (r13 >> 7) & 7;
        int kt  = r13 >> 10;
        int nt  = np * 2 + (reg >> 1);
        int r   = reg & 1;
        int nn  = nt * 8 + (ln >> 2);
        int t   = ln & 3;
        int k   = kt * 16 + r * 8 + t * 2;
        float w0, w1;
        if (l < 3) {
            const float* W = Ws + l * D * D;
            w0 = W[k * D + nn];
            w1 = W[(k + 1) * D + nn];
        } else {
            if (nn < LDIM) {
                w0 = Wmu[k * LDIM + nn];
                w1 = Wmu[(k + 1) * LDIM + nn];
            } else {
                w0 = Wlv[k * LDIM + (nn - LDIM)];
                w1 = Wlv[(k + 1) * LDIM + (nn - LDIM)];
            }
        }
        __half2 h2 = __floats2half2_rn(w0, w1);
        uint32_t u;
        memcpy(&u, &h2, 4);
        Wfrag[i] = u;
    }
    if (i < D) bcat[i] = (i < LDIM) ? bmu[i] : blv[i - LDIM];
}

__global__ void k_fill(const int* __restrict__ src, const int* __restrict__ dst,
                       int* wofs, int* col, int e) {
    int i = blockIdx.x * blockDim.x + threadIdx.x;
    if (i < e) {
        int d = dst[i];
        int pos = atomicAdd(&wofs[d], 1);
        col[pos] = src[i];
    }
}

// ---------------- fp16 tensor-core GEMM (m16n8k16, prepacked B, 128-row blocks) ----------------
__device__ __forceinline__ uint32_t h2_as_u32(__half2 h) {
    uint32_t r;
    memcpy(&r, &h, 4);
    return r;
}

__device__ __forceinline__ void mma16(float* d, const uint32_t* a,
                                      uint32_t b0, uint32_t b1) {
    asm volatile(
        "mma.sync.aligned.m16n8k16.row.col.f32.f16.f16.f32 "
        "{%0,%1,%2,%3}, {%4,%5,%6,%7}, {%8,%9}, {%0,%1,%2,%3};"
        : "+f"(d[0]), "+f"(d[1]), "+f"(d[2]), "+f"(d[3])
        : "r"(a[0]), "r"(a[1]), "r"(a[2]), "r"(a[3]), "r"(b0), "r"(b1));
}

// C_h[M,128] (fp16) = dinv[m] * (A'[M,128] @ B[128,128]).
// Block = 128 rows x 128 cols; 8 warps = 4 wm x 2 wn; each warp owns 2 m16 tiles,
// so each B fragment LDS feeds 2 A tiles (16 mma per kt per thread).
// Smem: As 8192 u32 (32KB) + Bs 8192 u32 (32KB) + SC/SF = 66560 B.
template <bool FUSE, bool WRITE_X>
__global__ __launch_bounds__(256) void k_gemm(const void* __restrict__ Araw,
                                              const uint4* __restrict__ Bfrag,
                                              __half2* __restrict__ C2,
                                              const float* __restrict__ dinv,
                                              const float* __restrict__ stats,
                                              const float* __restrict__ gamma,
                                              const float* __restrict__ beta,
                                              const float* __restrict__ xres,
                                              float* __restrict__ xout, int M) {
    extern __shared__ float sm[];
    uint32_t* As = (uint32_t*)sm;            // 8192 u32: [kt(8)][mt(8)][lane(32)][reg(4)]
    uint4*    Bs4 = (uint4*)(sm + 8192);     // 2048 u16x8: [kt(8)][np(8)][lane(32)]
    float* SC = sm + 16384;
    float* SF = sm + 16512;

    const int tid  = threadIdx.x;
    const int lane = tid & 31;
    const int warp = tid >> 5;
    const int wm = warp >> 1;                // 0..3, owns m-tiles wm*2, wm*2+1
    const int wn = warp & 1;
    const int row0 = blockIdx.x * 128;

    if (FUSE) {
        if (tid < 128) {
            float inv_n = 1.f / (float)M;
            float mean = stats[tid] * inv_n;
            float var  = stats[128 + tid] * inv_n - mean * mean;
            float s = gamma[tid] * rsqrtf(var + EPS);
            SC[tid] = s;
            SF[tid] = beta[tid] - mean * s;
        }
        __syncthreads();
    }

    // B fill: linear vectorized copy of prepacked fragments
    #pragma unroll
    for (int i = tid; i < 2048; i += 256) Bs4[i] = Bfrag[i];

    // A fill: fused BN/lrelu/residual + fp16 cvt into fragment layout
    #pragma unroll
    for (int idx = tid; idx < 8192; idx += 256) {
        int m = idx >> 6, k2 = idx & 63;
        int k = k2 * 2;
        int gr = row0 + m;
        float2 v = make_float2(0.f, 0.f);
        if (gr < M) {
            if (FUSE) {
                const __half2* Ah = (const __half2*)Araw;
                v = __half22float2(Ah[gr * 64 + k2]);
                float2 r2 = *(const float2*)&xres[gr * 128 + k];
                v.x = fmaf(v.x, SC[k],     SF[k]);
                v.y = fmaf(v.y, SC[k + 1], SF[k + 1]);
                v.x = ((v.x >= 0.f) ? v.x : SLOPE * v.x) + r2.x;
                v.y = ((v.y >= 0.f) ? v.y : SLOPE * v.y) + r2.y;
                if (WRITE_X) *(float2*)&xout[gr * 128 + k] = v;
            } else {
                v = *(const float2*)&((const float*)Araw)[gr * 128 + k];
            }
        }
        int kt = k >> 4, kk = k & 15;
        int mt = m >> 4, mi = m & 15;
        int reg = (mi >> 3) + 2 * (kk >> 3);
        int ln = (mi & 7) * 4 + ((kk & 7) >> 1);
        As[((kt * 8 + mt) * 32 + ln) * 4 + reg] =
            h2_as_u32(__floats2half2_rn(v.x, v.y));
    }
    __syncthreads();

    float acc[2][8][4];
    #pragma unroll
    for (int s2 = 0; s2 < 2; s2++)
        #pragma unroll
        for (int nt = 0; nt < 8; nt++)
            #pragma unroll
            for (int j = 0; j < 4; j++) acc[s2][nt][j] = 0.f;

    #pragma unroll
    for (int kt = 0; kt < 8; kt++) {
        uint4 av0 = *(const uint4*)&As[((kt * 8 + wm * 2)     * 32 + lane) * 4];
        uint4 av1 = *(const uint4*)&As[((kt * 8 + wm * 2 + 1) * 32 + lane) * 4];
        uint32_t af0[4] = {av0.x, av0.y, av0.z, av0.w};
        uint32_t af1[4] = {av1.x, av1.y, av1.z, av1.w};
        #pragma unroll
        for (int npl = 0; npl < 4; npl++) {
            uint4 bv = Bs4[(kt * 8 + wn * 4 + npl) * 32 + lane];
            mma16(acc[0][npl * 2],     af0, bv.x, bv.y);
            mma16(acc[0][npl * 2 + 1], af0, bv.z, bv.w);
            mma16(acc[1][npl * 2],     af1, bv.x, bv.y);
            mma16(acc[1][npl * 2 + 1], af1, bv.z, bv.w);
        }
    }

    const int g = lane >> 2, t = lane & 3;
    #pragma unroll
    for (int s2 = 0; s2 < 2; s2++) {
        const int r0 = row0 + (wm * 2 + s2) * 16 + g;
        const float sc0 = (r0 < M)     ? dinv[r0]     : 0.f;
        const float sc1 = (r0 + 8 < M) ? dinv[r0 + 8] : 0.f;
        #pragma unroll
        for (int nt = 0; nt < 8; nt++) {
            int c2 = wn * 32 + nt * 4 + t;
            if (r0 < M)
                C2[r0 * 64 + c2] =
                    __floats2half2_rn(acc[s2][nt][0] * sc0, acc[s2][nt][1] * sc0);
            if (r0 + 8 < M)
                C2[(r0 + 8) * 64 + c2] =
                    __floats2half2_rn(acc[s2][nt][2] * sc1, acc[s2][nt][3] * sc1);
        }
    }
}

// ---------------- propagation (+ fused BN statistics) ----------------
__device__ __forceinline__ void acc_add(float4& a, uint2 r) {
    float2 f0 = __half22float2(*reinterpret_cast<__half2*>(&r.x));
    float2 f1 = __half22float2(*reinterpret_cast<__half2*>(&r.y));
    a.x += f0.x; a.y += f0.y; a.z += f1.x; a.w += f1.y;
}

// h (fp16, pre-scaled by dinv): out[d] = dinv[d]*(sum_s h[s] + h[d]) + b.
// SPLIT=false: writes fp16 agg. SPLIT=true: writes fp32 mu/logvar.
template <bool SPLIT, bool STATS>
__global__ __launch_bounds__(256) void k_prop(const uint2* __restrict__ hh,
                                              const float* __restrict__ dinv,
                                              const int* __restrict__ rowptr,
                                              const int* __restrict__ col,
                                              const float* __restrict__ bias,
                                              uint2* __restrict__ out_h,
                                              float4* __restrict__ out_a,
                                              float4* __restrict__ out_b,
                                              float* __restrict__ stats, int n) {
    __shared__ float s_red[256];
    const int lane = threadIdx.x & 31;
    const int warp = threadIdx.x >> 5;
    if (STATS) {
        s_red[threadIdx.x] = 0.f;
        __syncthreads();
    }
    const float4 b4 = *(const float4*)(bias + lane * 4);
    float4 ps = make_float4(0.f, 0.f, 0.f, 0.f);
    float4 pq = make_float4(0.f, 0.f, 0.f, 0.f);
    const int base = blockIdx.x * 64 + warp * 8;
    #pragma unroll 1
    for (int p = 0; p < 4; p++) {
        const int w0 = base + 2 * p;
        const int w1 = w0 + 1;
        if (w0 >= n) break;
        const bool has1 = (w1 < n);
        float4 A0 = make_float4(0.f, 0.f, 0.f, 0.f);
        float4 A1 = make_float4(0.f, 0.f, 0.f, 0.f);
        acc_add(A0, hh[w0 * 32 + lane]);
        if (has1) acc_add(A1, hh[w1 * 32 + lane]);
        int e0 = rowptr[w0];
        int f0 = rowptr[w0 + 1];
        int e1 = has1 ? rowptr[w1] : 0;
        int f1 = has1 ? rowptr[w1 + 1] : 0;
        while (e0 + 2 <= f0 && e1 + 2 <= f1) {
            int c0 = col[e0], c1 = col[e0 + 1], c2 = col[e1], c3 = col[e1 + 1];
            uint2 u0 = hh[c0 * 32 + lane];
            uint2 u1 = hh[c1 * 32 + lane];
            uint2 u2 = hh[c2 * 32 + lane];
            uint2 u3 = hh[c3 * 32 + lane];
            acc_add(A0, u0); acc_add(A0, u1);
            acc_add(A1, u2); acc_add(A1, u3);
            e0 += 2; e1 += 2;
        }
        for (; e0 + 4 <= f0; e0 += 4) {
            int c0 = col[e0], c1 = col[e0 + 1], c2 = col[e0 + 2], c3 = col[e0 + 3];
            uint2 u0 = hh[c0 * 32 + lane];
            uint2 u1 = hh[c1 * 32 + lane];
            uint2 u2 = hh[c2 * 32 + lane];
            uint2 u3 = hh[c3 * 32 + lane];
            acc_add(A0, u0); acc_add(A0, u1);
            acc_add(A0, u2); acc_add(A0, u3);
        }
        for (; e0 < f0; e0++) acc_add(A0, hh[col[e0] * 32 + lane]);
        for (; e1 + 4 <= f1; e1 += 4) {
            int c0 = col[e1], c1 = col[e1 + 1], c2 = col[e1 + 2], c3 = col[e1 + 3];
            uint2 u0 = hh[c0 * 32 + lane];
            uint2 u1 = hh[c1 * 32 + lane];
            uint2 u2 = hh[c2 * 32 + lane];
            uint2 u3 = hh[c3 * 32 + lane];
            acc_add(A1, u0); acc_add(A1, u1);
            acc_add(A1, u2); acc_add(A1, u3);
        }
        for (; e1 < f1; e1++) acc_add(A1, hh[col[e1] * 32 + lane]);

        #pragma unroll
        for (int q = 0; q < 2; q++) {
            int w = q ? w1 : w0;
            if (q && !has1) break;
            float dd = dinv[w];
            float4 src = q ? A1 : A0;
            float4 acc;
            acc.x = fmaf(src.x, dd, b4.x);
            acc.y = fmaf(src.y, dd, b4.y);
            acc.z = fmaf(src.z, dd, b4.z);
            acc.w = fmaf(src.w, dd, b4.w);
            if (STATS) {
                ps.x += acc.x; ps.y += acc.y; ps.z += acc.z; ps.w += acc.w;
                pq.x += acc.x * acc.x; pq.y += acc.y * acc.y;
                pq.z += acc.z * acc.z; pq.w += acc.w * acc.w;
            }
            if (!SPLIT) {
                uint2 o;
                __half2 h0 = __floats2half2_rn(acc.x, acc.y);
                __half2 h1 = __floats2half2_rn(acc.z, acc.w);
                memcpy(&o.x, &h0, 4);
                memcpy(&o.y, &h1, 4);
                out_h[w * 32 + lane] = o;
            } else {
                if (lane < 16) out_a[w * 16 + lane]        = acc;   // mu
                else           out_b[w * 16 + (lane - 16)] = acc;   // logvar
            }
        }
    }
    if (STATS) {
        atomicAdd(&s_red[lane * 4 + 0], ps.x);
        atomicAdd(&s_red[lane * 4 + 1], ps.y);
        atomicAdd(&s_red[lane * 4 + 2], ps.z);
        atomicAdd(&s_red[lane * 4 + 3], ps.w);
        atomicAdd(&s_red[128 + lane * 4 + 0], pq.x);
        atomicAdd(&s_red[128 + lane * 4 + 1], pq.y);
        atomicAdd(&s_red[128 + lane * 4 + 2], pq.z);
        atomicAdd(&s_red[128 + lane * 4 + 3], pq.w);
        __syncthreads();
        atomicAdd(&stats[threadIdx.x], s_red[threadIdx.x]);
    }
}

// ---------------- launcher ----------------
extern "C" void kernel_launch(void* const* d_in, const int* in_sizes, int n_in,
                              void* d_out, int out_size) {
    const float* x     = (const float*)d_in[0];
    const int*   ei    = (const int*)d_in[1];     // int32 (jax x64 disabled)
    const float* Ws    = (const float*)d_in[2];
    const float* bs    = (const float*)d_in[3];
    const float* Wmu   = (const float*)d_in[4];
    const float* bmu   = (const float*)d_in[5];
    const float* Wlv   = (const float*)d_in[6];
    const float* blv   = (const float*)d_in[7];
    const float* gamma = (const float*)d_in[8];
    const float* beta  = (const float*)d_in[9];

    const int n = in_sizes[0] / D;
    const int e = in_sizes[1] / 2;
    float* out = (float*)d_out;

    __half *h, *aggA, *aggB;
    float *x1, *x2, *dinv, *stats, *bcat;
    uint32_t* Wfrag;
    int *counts, *rowptr, *linc, *bsums, *wofs, *col;
    cudaGetSymbolAddress((void**)&h,      g_h);
    cudaGetSymbolAddress((void**)&aggA,   g_aggA);
    cudaGetSymbolAddress((void**)&aggB,   g_aggB);
    cudaGetSymbolAddress((void**)&x1,     g_x1);
    cudaGetSymbolAddress((void**)&x2,     g_x2);
    cudaGetSymbolAddress((void**)&dinv,   g_dinv);
    cudaGetSymbolAddress((void**)&stats,  g_stats);
    cudaGetSymbolAddress((void**)&Wfrag,  g_Wfrag);
    cudaGetSymbolAddress((void**)&bcat,   g_bcat);
    cudaGetSymbolAddress((void**)&counts, g_counts);
    cudaGetSymbolAddress((void**)&rowptr, g_rowptr);
    cudaGetSymbolAddress((void**)&linc,   g_linc);
    cudaGetSymbolAddress((void**)&bsums,  g_bsums);
    cudaGetSymbolAddress((void**)&wofs,   g_wofs);
    cudaGetSymbolAddress((void**)&col,    g_col);

    const int* srcp = ei;
    const int* dstp = ei + e;

    const int SMEM = 16640 * (int)sizeof(float);   // 66560 B
    cudaFuncSetAttribute(k_gemm<false, false>,
                         cudaFuncAttributeMaxDynamicSharedMemorySize, SMEM);
    cudaFuncSetAttribute(k_gemm<true, true>,
                         cudaFuncAttributeMaxDynamicSharedMemorySize, SMEM);
    cudaFuncSetAttribute(k_gemm<true, false>,
                         cudaFuncAttributeMaxDynamicSharedMemorySize, SMEM);

    const int gemm_grid = (n + 127) / 128;
    const int prop_grid = (n + 63) / 64;
    const int nb = (n + 1023) / 1024;

    // preprocessing; k_gemm stays the 4th kernel (profiler captures it)
    k_count<<<(e + 255) / 256, 256>>>(dstp, counts, e);                       // 1
    k_scan1<<<nb, 1024>>>(counts, linc, bsums, stats, n);                     // 2
    k_aux_pack<<<(n + 255) / 256, 256>>>(linc, bsums, counts, rowptr, wofs,   // 3
                                         dinv, Ws, Wmu, Wlv, bmu, blv,
                                         Wfrag, bcat, n);
    k_gemm<false, false><<<gemm_grid, 256, SMEM>>>(x, (const uint4*)Wfrag,    // 4
                                                   (__half2*)h, dinv, nullptr,
                                                   nullptr, nullptr, nullptr,
                                                   nullptr, n);
    k_fill<<<(e + 255) / 256, 256>>>(srcp, dstp, wofs, col, e);               // 5

    // layer 0 prop
    k_prop<false, true><<<prop_grid, 256>>>((const uint2*)h, dinv, rowptr, col,
                                            bs, (uint2*)aggA, nullptr, nullptr,
                                            stats, n);
    // layer 1
    k_gemm<true, true><<<gemm_grid, 256, SMEM>>>(aggA, (const uint4*)(Wfrag + 8192),
                                                 (__half2*)h, dinv, stats,
                                                 gamma, beta, x, x1, n);
    k_prop<false, true><<<prop_grid, 256>>>((const uint2*)h, dinv, rowptr, col,
                                            bs + D, (uint2*)aggB, nullptr, nullptr,
                                            stats + 256, n);
    // layer 2
    k_gemm<true, true><<<gemm_grid, 256, SMEM>>>(aggB, (const uint4*)(Wfrag + 16384),
                                                 (__half2*)h, dinv, stats + 256,
                                                 gamma, beta, x1, x2, n);
    k_prop<false, true><<<prop_grid, 256>>>((const uint2*)h, dinv, rowptr, col,
                                            bs + 2 * D, (uint2*)aggA, nullptr,
                                            nullptr, stats + 512, n);
    // heads
    k_gemm<true, false><<<gemm_grid, 256, SMEM>>>(aggA, (const uint4*)(Wfrag + 24576),
                                                  (__half2*)h, dinv, stats + 512,
                                                  gamma, beta, x2, nullptr, n);
    k_prop<true, false><<<prop_grid, 256>>>((const uint2*)h, dinv, rowptr, col,
                                            bcat, nullptr, (float4*)out,
                                            (float4*)(out + (size_t)n * LDIM),
                                            nullptr, n);
}

// round 16
// speedup vs baseline: 1.0903x; 1.0903x over previous
#include <cuda_runtime.h>
#include <cuda_fp16.h>
#include <cstdint>
#include <cstring>

#define D     128
#define LDIM  64
#define NMAX  50000
#define EMAX  625000
#define EPS   1e-5f
#define SLOPE 0.01f

// ---------------- scratch (static device globals; no allocation) ----------------
__device__ __half   g_h   [NMAX * D];        // GEMM output, fp16, pre-scaled by dinv
__device__ __half   g_aggA[NMAX * D];        // prop output (pre-BN), fp16
__device__ __half   g_aggB[NMAX * D];
__device__ float    g_x1  [NMAX * D];
__device__ float    g_x2  [NMAX * D];
__device__ float    g_dinv[NMAX];
__device__ int      g_counts[NMAX];          // invariant: all-zero at entry
__device__ int      g_rowptr[NMAX + 1];
__device__ int      g_linc[NMAX];
__device__ int      g_bsums[128];
__device__ int      g_wofs[NMAX];
__device__ int      g_col[EMAX];
__device__ float    g_stats[3 * 2 * D];
__device__ uint32_t g_Wfrag[4 * 8192];       // 4 matrices, fp16 fragment-major
__device__ float    g_bcat[D];

// ---------------- graph preprocessing ----------------
__global__ void k_count(const int* __restrict__ dst, int* counts, int e) {
    int i = blockIdx.x * blockDim.x + threadIdx.x;
    if (i < e) atomicAdd(&counts[dst[i]], 1);
}

// per-block (1024) inclusive scan; block 0 also zeroes BN stats
__global__ __launch_bounds__(1024) void k_scan1(const int* __restrict__ counts,
                                                int* linc, int* bsums,
                                                float* stats, int n) {
    __shared__ int ws[32];
    const int tid = threadIdx.x, lane = tid & 31, wid = tid >> 5;
    if (blockIdx.x == 0 && tid < 3 * 2 * D) stats[tid] = 0.f;
    int i = blockIdx.x * 1024 + tid;
    int v = (i < n) ? counts[i] : 0;
    int s = v;
    #pragma unroll
    for (int off = 1; off < 32; off <<= 1) {
        int t = __shfl_up_sync(0xffffffffu, s, off);
        if (lane >= off) s += t;
    }
    if (lane == 31) ws[wid] = s;
    __syncthreads();
    if (wid == 0) {
        int t2 = ws[lane];
        #pragma unroll
        for (int off = 1; off < 32; off <<= 1) {
            int t = __shfl_up_sync(0xffffffffu, t2, off);
            if (lane >= off) t2 += t;
        }
        ws[lane] = t2;
    }
    __syncthreads();
    int inc = s + (wid ? ws[wid - 1] : 0);
    if (i < n) linc[i] = inc;
    if (tid == 1023) bsums[blockIdx.x] = inc;
}

// finalize rowptr/wofs/dinv + inline scan2 + restore counts + pre-pack weights
// into fp16 fragment-major layout: idx = ((kt*8+np)*32+ln)*4 + (nt&1)*2 + r
__global__ __launch_bounds__(256) void k_aux_pack(
        const int* __restrict__ linc, const int* __restrict__ bsums,
        int* counts, int* rowptr, int* wofs, float* dinv,
        const float* __restrict__ Ws,
        const float* __restrict__ Wmu, const float* __restrict__ Wlv,
        const float* __restrict__ bmu, const float* __restrict__ blv,
        uint32_t* Wfrag, float* bcat, int n) {
    __shared__ int s_pre;
    const int tid = threadIdx.x;
    if (tid == 0) s_pre = 0;
    __syncthreads();
    const int j = (int)(blockIdx.x >> 2);
    if (tid < j) atomicAdd(&s_pre, bsums[tid]);
    __syncthreads();
    const int pre = s_pre;
    int i = blockIdx.x * 256 + tid;
    if (i < n) {
        int c = counts[i];
        int rp1 = pre + linc[i];
        rowptr[i + 1] = rp1;
        wofs[i] = rp1 - c;
        dinv[i] = rsqrtf((float)(c + 1));     // +1 self-loop
        counts[i] = 0;
        if (i == 0) rowptr[0] = 0;
    }
    if (i < 4 * 8192) {
        int l   = i >> 13;
        int r13 = i & 8191;
        int reg = r13 & 3;
        int ln  = (r13 >> 2) & 31;
        int np  = (r13 >> 7) & 7;
        int kt  = r13 >> 10;
        int nt  = np * 2 + (reg >> 1);
        int r   = reg & 1;
        int nn  = nt * 8 + (ln >> 2);
        int t   = ln & 3;
        int k   = kt * 16 + r * 8 + t * 2;
        float w0, w1;
        if (l < 3) {
            const float* W = Ws + l * D * D;
            w0 = W[k * D + nn];
            w1 = W[(k + 1) * D + nn];
        } else {
            if (nn < LDIM) {
                w0 = Wmu[k * LDIM + nn];
                w1 = Wmu[(k + 1) * LDIM + nn];
            } else {
                w0 = Wlv[k * LDIM + (nn - LDIM)];
                w1 = Wlv[(k + 1) * LDIM + (nn - LDIM)];
            }
        }
        __half2 h2 = __floats2half2_rn(w0, w1);
        uint32_t u;
        memcpy(&u, &h2, 4);
        Wfrag[i] = u;
    }
    if (i < D) bcat[i] = (i < LDIM) ? bmu[i] : blv[i - LDIM];
}

__global__ void k_fill(const int* __restrict__ src, const int* __restrict__ dst,
                       int* wofs, int* col, int e) {
    int i = blockIdx.x * blockDim.x + threadIdx.x;
    if (i < e) {
        int d = dst[i];
        int pos = atomicAdd(&wofs[d], 1);
        col[pos] = src[i];
    }
}

// ---------------- fp16 tensor-core GEMM (m16n8k16, prepacked B, padded As) ----------------
__device__ __forceinline__ uint32_t h2_as_u32(__half2 h) {
    uint32_t r;
    memcpy(&r, &h, 4);
    return r;
}

__device__ __forceinline__ void mma16(float* d, const uint32_t* a,
                                      uint32_t b0, uint32_t b1) {
    asm volatile(
        "mma.sync.aligned.m16n8k16.row.col.f32.f16.f16.f32 "
        "{%0,%1,%2,%3}, {%4,%5,%6,%7}, {%8,%9}, {%0,%1,%2,%3};"
        : "+f"(d[0]), "+f"(d[1]), "+f"(d[2]), "+f"(d[3])
        : "r"(a[0]), "r"(a[1]), "r"(a[2]), "r"(a[3]), "r"(b0), "r"(b1));
}

// C_h[M,128] (fp16) = dinv[m] * (A'[M,128] @ B[128,128]).
// 64-row blocks (R14 geometry, proven). As group stride padded 128->132 words:
// store banks gain 4*g entropy -> A-fill conflicts 4-way -> 2-way; reads stay clean.
// Smem: As 4224 u32 + Bs 8192 u32 + SC/SF 256 = 50688 B.
template <bool FUSE, bool WRITE_X>
__global__ __launch_bounds__(256) void k_gemm(const void* __restrict__ Araw,
                                              const uint4* __restrict__ Bfrag,
                                              __half2* __restrict__ C2,
                                              const float* __restrict__ dinv,
                                              const float* __restrict__ stats,
                                              const float* __restrict__ gamma,
                                              const float* __restrict__ beta,
                                              const float* __restrict__ xres,
                                              float* __restrict__ xout, int M) {
    extern __shared__ float sm[];
    uint32_t* As = (uint32_t*)sm;            // 4224 u32: [g(32) x 132] padded groups
    uint4*    Bs4 = (uint4*)(sm + 4224);     // 2048 u16x8: [kt(8)][np(8)][lane(32)]
    float* SC = sm + 12416;
    float* SF = sm + 12544;

    const int tid  = threadIdx.x;
    const int lane = tid & 31;
    const int warp = tid >> 5;
    const int wm = warp >> 1;
    const int wn = warp & 1;
    const int row0 = blockIdx.x * 64;

    if (FUSE) {
        if (tid < 128) {
            float inv_n = 1.f / (float)M;
            float mean = stats[tid] * inv_n;
            float var  = stats[128 + tid] * inv_n - mean * mean;
            float s = gamma[tid] * rsqrtf(var + EPS);
            SC[tid] = s;
            SF[tid] = beta[tid] - mean * s;
        }
        __syncthreads();
    }

    // B fill: linear vectorized copy of prepacked fragments
    #pragma unroll
    for (int i = tid; i < 2048; i += 256) Bs4[i] = Bfrag[i];

    // A fill: fused BN/lrelu/residual + fp16 cvt into padded fragment layout
    #pragma unroll
    for (int idx = tid; idx < 4096; idx += 256) {
        int m = idx >> 6, k2 = idx & 63;
        int k = k2 * 2;
        int gr = row0 + m;
        float2 v = make_float2(0.f, 0.f);
        if (gr < M) {
            if (FUSE) {
                const __half2* Ah = (const __half2*)Araw;
                v = __half22float2(Ah[gr * 64 + k2]);
                float2 r2 = *(const float2*)&xres[gr * 128 + k];
                v.x = fmaf(v.x, SC[k],     SF[k]);
                v.y = fmaf(v.y, SC[k + 1], SF[k + 1]);
                v.x = ((v.x >= 0.f) ? v.x : SLOPE * v.x) + r2.x;
                v.y = ((v.y >= 0.f) ? v.y : SLOPE * v.y) + r2.y;
                if (WRITE_X) *(float2*)&xout[gr * 128 + k] = v;
            } else {
                v = *(const float2*)&((const float*)Araw)[gr * 128 + k];
            }
        }
        int kt = k >> 4, kk = k & 15;
        int mt = m >> 4, mi = m & 15;
        int reg = (mi >> 3) + 2 * (kk >> 3);
        int ln = (mi & 7) * 4 + ((kk & 7) >> 1);
        As[(kt * 4 + mt) * 132 + ln * 4 + reg] =
            h2_as_u32(__floats2half2_rn(v.x, v.y));
    }
    __syncthreads();

    float acc[8][4];
    #pragma unroll
    for (int nt = 0; nt < 8; nt++)
        #pragma unroll
        for (int j = 0; j < 4; j++) acc[nt][j] = 0.f;

    #pragma unroll
    for (int kt = 0; kt < 8; kt++) {
        uint4 av = *(const uint4*)&As[(kt * 4 + wm) * 132 + lane * 4];
        uint32_t af[4] = {av.x, av.y, av.z, av.w};
        #pragma unroll
        for (int npl = 0; npl < 4; npl++) {
            uint4 bv = Bs4[(kt * 8 + wn * 4 + npl) * 32 + lane];
            mma16(acc[npl * 2],     af, bv.x, bv.y);
            mma16(acc[npl * 2 + 1], af, bv.z, bv.w);
        }
    }

    const int g = lane >> 2, t = lane & 3;
    const int r0 = row0 + wm * 16 + g;
    const float s0 = (r0 < M)     ? dinv[r0]     : 0.f;
    const float s1 = (r0 + 8 < M) ? dinv[r0 + 8] : 0.f;
    #pragma unroll
    for (int nt = 0; nt < 8; nt++) {
        int c2 = wn * 32 + nt * 4 + t;
        if (r0 < M)
            C2[r0 * 64 + c2] = __floats2half2_rn(acc[nt][0] * s0, acc[nt][1] * s0);
        if (r0 + 8 < M)
            C2[(r0 + 8) * 64 + c2] = __floats2half2_rn(acc[nt][2] * s1, acc[nt][3] * s1);
    }
}

// ---------------- propagation (+ fused BN statistics) ----------------
__device__ __forceinline__ void acc_add(float4& a, uint2 r) {
    float2 f0 = __half22float2(*reinterpret_cast<__half2*>(&r.x));
    float2 f1 = __half22float2(*reinterpret_cast<__half2*>(&r.y));
    a.x += f0.x; a.y += f0.y; a.z += f1.x; a.w += f1.y;
}

// h (fp16, pre-scaled by dinv): out[d] = dinv[d]*(sum_s h[s] + h[d]) + b.
// Pairs of nodes; joint phase now 4 edges/node = 8 gathers in flight (MLP 8).
template <bool SPLIT, bool STATS>
__global__ __launch_bounds__(256) void k_prop(const uint2* __restrict__ hh,
                                              const float* __restrict__ dinv,
                                              const int* __restrict__ rowptr,
                                              const int* __restrict__ col,
                                              const float* __restrict__ bias,
                                              uint2* __restrict__ out_h,
                                              float4* __restrict__ out_a,
                                              float4* __restrict__ out_b,
                                              float* __restrict__ stats, int n) {
    __shared__ float s_red[256];
    const int lane = threadIdx.x & 31;
    const int warp = threadIdx.x >> 5;
    if (STATS) {
        s_red[threadIdx.x] = 0.f;
        __syncthreads();
    }
    const float4 b4 = *(const float4*)(bias + lane * 4);
    float4 ps = make_float4(0.f, 0.f, 0.f, 0.f);
    float4 pq = make_float4(0.f, 0.f, 0.f, 0.f);
    const int base = blockIdx.x * 64 + warp * 8;
    #pragma unroll 1
    for (int p = 0; p < 4; p++) {
        const int w0 = base + 2 * p;
        const int w1 = w0 + 1;
        if (w0 >= n) break;
        const bool has1 = (w1 < n);
        float4 A0 = make_float4(0.f, 0.f, 0.f, 0.f);
        float4 A1 = make_float4(0.f, 0.f, 0.f, 0.f);
        acc_add(A0, hh[w0 * 32 + lane]);
        if (has1) acc_add(A1, hh[w1 * 32 + lane]);
        int e0 = rowptr[w0];
        int f0 = rowptr[w0 + 1];
        int e1 = has1 ? rowptr[w1] : 0;
        int f1 = has1 ? rowptr[w1 + 1] : 0;
        // joint-8 phase: 8 independent gathers in flight (4 per node)
        while (e0 + 4 <= f0 && e1 + 4 <= f1) {
            int c0 = col[e0], c1 = col[e0 + 1], c2 = col[e0 + 2], c3 = col[e0 + 3];
            int c4 = col[e1], c5 = col[e1 + 1], c6 = col[e1 + 2], c7 = col[e1 + 3];
            uint2 u0 = hh[c0 * 32 + lane];
            uint2 u1 = hh[c1 * 32 + lane];
            uint2 u2 = hh[c2 * 32 + lane];
            uint2 u3 = hh[c3 * 32 + lane];
            uint2 u4 = hh[c4 * 32 + lane];
            uint2 u5 = hh[c5 * 32 + lane];
            uint2 u6 = hh[c6 * 32 + lane];
            uint2 u7 = hh[c7 * 32 + lane];
            acc_add(A0, u0); acc_add(A0, u1); acc_add(A0, u2); acc_add(A0, u3);
            acc_add(A1, u4); acc_add(A1, u5); acc_add(A1, u6); acc_add(A1, u7);
            e0 += 4; e1 += 4;
        }
        // joint-4 phase
        while (e0 + 2 <= f0 && e1 + 2 <= f1) {
            int c0 = col[e0], c1 = col[e0 + 1], c2 = col[e1], c3 = col[e1 + 1];
            uint2 u0 = hh[c0 * 32 + lane];
            uint2 u1 = hh[c1 * 32 + lane];
            uint2 u2 = hh[c2 * 32 + lane];
            uint2 u3 = hh[c3 * 32 + lane];
            acc_add(A0, u0); acc_add(A0, u1);
            acc_add(A1, u2); acc_add(A1, u3);
            e0 += 2; e1 += 2;
        }
        // drain node 0
        for (; e0 + 4 <= f0; e0 += 4) {
            int c0 = col[e0], c1 = col[e0 + 1], c2 = col[e0 + 2], c3 = col[e0 + 3];
            uint2 u0 = hh[c0 * 32 + lane];
            uint2 u1 = hh[c1 * 32 + lane];
            uint2 u2 = hh[c2 * 32 + lane];
            uint2 u3 = hh[c3 * 32 + lane];
            acc_add(A0, u0); acc_add(A0, u1);
            acc_add(A0, u2); acc_add(A0, u3);
        }
        for (; e0 < f0; e0++) acc_add(A0, hh[col[e0] * 32 + lane]);
        // drain node 1
        for (; e1 + 4 <= f1; e1 += 4) {
            int c0 = col[e1], c1 = col[e1 + 1], c2 = col[e1 + 2], c3 = col[e1 + 3];
            uint2 u0 = hh[c0 * 32 + lane];
            uint2 u1 = hh[c1 * 32 + lane];
            uint2 u2 = hh[c2 * 32 + lane];
            uint2 u3 = hh[c3 * 32 + lane];
            acc_add(A1, u0); acc_add(A1, u1);
            acc_add(A1, u2); acc_add(A1, u3);
        }
        for (; e1 < f1; e1++) acc_add(A1, hh[col[e1] * 32 + lane]);

        #pragma unroll
        for (int q = 0; q < 2; q++) {
            int w = q ? w1 : w0;
            if (q && !has1) break;
            float dd = dinv[w];
            float4 src = q ? A1 : A0;
            float4 acc;
            acc.x = fmaf(src.x, dd, b4.x);
            acc.y = fmaf(src.y, dd, b4.y);
            acc.z = fmaf(src.z, dd, b4.z);
            acc.w = fmaf(src.w, dd, b4.w);
            if (STATS) {
                ps.x += acc.x; ps.y += acc.y; ps.z += acc.z; ps.w += acc.w;
                pq.x += acc.x * acc.x; pq.y += acc.y * acc.y;
                pq.z += acc.z * acc.z; pq.w += acc.w * acc.w;
            }
            if (!SPLIT) {
                uint2 o;
                __half2 h0 = __floats2half2_rn(acc.x, acc.y);
                __half2 h1 = __floats2half2_rn(acc.z, acc.w);
                memcpy(&o.x, &h0, 4);
                memcpy(&o.y, &h1, 4);
                out_h[w * 32 + lane] = o;
            } else {
                if (lane < 16) out_a[w * 16 + lane]        = acc;   // mu
                else           out_b[w * 16 + (lane - 16)] = acc;   // logvar
            }
        }
    }
    if (STATS) {
        atomicAdd(&s_red[lane * 4 + 0], ps.x);
        atomicAdd(&s_red[lane * 4 + 1], ps.y);
        atomicAdd(&s_red[lane * 4 + 2], ps.z);
        atomicAdd(&s_red[lane * 4 + 3], ps.w);
        atomicAdd(&s_red[128 + lane * 4 + 0], pq.x);
        atomicAdd(&s_red[128 + lane * 4 + 1], pq.y);
        atomicAdd(&s_red[128 + lane * 4 + 2], pq.z);
        atomicAdd(&s_red[128 + lane * 4 + 3], pq.w);
        __syncthreads();
        atomicAdd(&stats[threadIdx.x], s_red[threadIdx.x]);
    }
}

// ---------------- launcher ----------------
extern "C" void kernel_launch(void* const* d_in, const int* in_sizes, int n_in,
                              void* d_out, int out_size) {
    const float* x     = (const float*)d_in[0];
    const int*   ei    = (const int*)d_in[1];     // int32 (jax x64 disabled)
    const float* Ws    = (const float*)d_in[2];
    const float* bs    = (const float*)d_in[3];
    const float* Wmu   = (const float*)d_in[4];
    const float* bmu   = (const float*)d_in[5];
    const float* Wlv   = (const float*)d_in[6];
    const float* blv   = (const float*)d_in[7];
    const float* gamma = (const float*)d_in[8];
    const float* beta  = (const float*)d_in[9];

    const int n = in_sizes[0] / D;
    const int e = in_sizes[1] / 2;
    float* out = (float*)d_out;

    __half *h, *aggA, *aggB;
    float *x1, *x2, *dinv, *stats, *bcat;
    uint32_t* Wfrag;
    int *counts, *rowptr, *linc, *bsums, *wofs, *col;
    cudaGetSymbolAddress((void**)&h,      g_h);
    cudaGetSymbolAddress((void**)&aggA,   g_aggA);
    cudaGetSymbolAddress((void**)&aggB,   g_aggB);
    cudaGetSymbolAddress((void**)&x1,     g_x1);
    cudaGetSymbolAddress((void**)&x2,     g_x2);
    cudaGetSymbolAddress((void**)&dinv,   g_dinv);
    cudaGetSymbolAddress((void**)&stats,  g_stats);
    cudaGetSymbolAddress((void**)&Wfrag,  g_Wfrag);
    cudaGetSymbolAddress((void**)&bcat,   g_bcat);
    cudaGetSymbolAddress((void**)&counts, g_counts);
    cudaGetSymbolAddress((void**)&rowptr, g_rowptr);
    cudaGetSymbolAddress((void**)&linc,   g_linc);
    cudaGetSymbolAddress((void**)&bsums,  g_bsums);
    cudaGetSymbolAddress((void**)&wofs,   g_wofs);
    cudaGetSymbolAddress((void**)&col,    g_col);

    const int* srcp = ei;
    const int* dstp = ei + e;

    const int SMEM = 12672 * (int)sizeof(float);   // 50688 B
    cudaFuncSetAttribute(k_gemm<false, false>,
                         cudaFuncAttributeMaxDynamicSharedMemorySize, SMEM);
    cudaFuncSetAttribute(k_gemm<true, true>,
                         cudaFuncAttributeMaxDynamicSharedMemorySize, SMEM);
    cudaFuncSetAttribute(k_gemm<true, false>,
                         cudaFuncAttributeMaxDynamicSharedMemorySize, SMEM);

    const int gemm_grid = (n + 63) / 64;
    const int prop_grid = (n + 63) / 64;
    const int nb = (n + 1023) / 1024;

    // preprocessing; k_gemm stays the 4th kernel (profiler captures it)
    k_count<<<(e + 255) / 256, 256>>>(dstp, counts, e);                       // 1
    k_scan1<<<nb, 1024>>>(counts, linc, bsums, stats, n);                     // 2
    k_aux_pack<<<(n + 255) / 256, 256>>>(linc, bsums, counts, rowptr, wofs,   // 3
                                         dinv, Ws, Wmu, Wlv, bmu, blv,
                                         Wfrag, bcat, n);
    k_gemm<false, false><<<gemm_grid, 256, SMEM>>>(x, (const uint4*)Wfrag,    // 4
                                                   (__half2*)h, dinv, nullptr,
                                                   nullptr, nullptr, nullptr,
                                                   nullptr, n);
    k_fill<<<(e + 255) / 256, 256>>>(srcp, dstp, wofs, col, e);               // 5

    // layer 0 prop
    k_prop<false, true><<<prop_grid, 256>>>((const uint2*)h, dinv, rowptr, col,
                                            bs, (uint2*)aggA, nullptr, nullptr,
                                            stats, n);
    // layer 1
    k_gemm<true, true><<<gemm_grid, 256, SMEM>>>(aggA, (const uint4*)(Wfrag + 8192),
                                                 (__half2*)h, dinv, stats,
                                                 gamma, beta, x, x1, n);
    k_prop<false, true><<<prop_grid, 256>>>((const uint2*)h, dinv, rowptr, col,
                                            bs + D, (uint2*)aggB, nullptr, nullptr,
                                            stats + 256, n);
    // layer 2
    k_gemm<true, true><<<gemm_grid, 256, SMEM>>>(aggB, (const uint4*)(Wfrag + 16384),
                                                 (__half2*)h, dinv, stats + 256,
                                                 gamma, beta, x1, x2, n);
    k_prop<false, true><<<prop_grid, 256>>>((const uint2*)h, dinv, rowptr, col,
                                            bs + 2 * D, (uint2*)aggA, nullptr,
                                            nullptr, stats + 512, n);
    // heads
    k_gemm<true, false><<<gemm_grid, 256, SMEM>>>(aggA, (const uint4*)(Wfrag + 24576),
                                                  (__half2*)h, dinv, stats + 512,
                                                  gamma, beta, x2, nullptr, n);
    k_prop<true, false><<<prop_grid, 256>>>((const uint2*)h, dinv, rowptr, col,
                                            bcat, nullptr, (float4*)out,
                                            (float4*)(out + (size_t)n * LDIM),
                                            nullptr, n);
}